// round 12
// baseline (speedup 1.0000x reference)
#include <cuda_runtime.h>
#include <math.h>

#define NN 50000          // N_NODES == M_NODES
#define KNBR 32
#define F 128
#define WSIZE 3
#define RPB 32            // rows per block (4 warps x 8 rows)

typedef unsigned long long ull;

// Scratch (device globals: allocation-free per harness rules)
__device__ float g_h[(size_t)NN * F];     // h = input @ W  (fp32)
__device__ float g_hc1[NN];               // fl32( fp64-accurate h . c1 )
__device__ float g_hc2[NN];               // fl32( fp64-accurate h . c2 )

// ---- packed f32x2 helpers ----
static __device__ __forceinline__ ull pack2(float lo, float hi) {
    ull r;
    asm("mov.b64 %0, {%1, %2};" : "=l"(r) : "f"(lo), "f"(hi));
    return r;
}
static __device__ __forceinline__ void unpack2(ull v, float& lo, float& hi) {
    asm("mov.b64 {%0, %1}, %2;" : "=f"(lo), "=f"(hi) : "l"(v));
}
static __device__ __forceinline__ void ffma2(ull& d, ull a, ull b) {
    asm("fma.rn.f32x2 %0, %1, %2, %0;" : "+l"(d) : "l"(a), "l"(b));
}

// ============================================================================
// Kernel A: h = input @ W — PURE GEMM, exact R10 configuration (57.2 us).
// ARITHMETIC CONTRACT (bitwise, frozen): for each (row, col),
//   acc.lo = sum over even k ascending of in[k]*W[k][c]
//   acc.hi = sum over odd  k ascending;  h = acc.lo + acc.hi
// block = 128 threads (4 warps), 32 rows/block, 8 rows/warp, 4 cols/lane.
// ============================================================================
__global__ void __launch_bounds__(128) gemm_kernel(
    const float* __restrict__ inp,
    const float* __restrict__ W)
{
    __shared__ float s_in[RPB][F];   // 16 KB

    const int tid  = threadIdx.x;
    const int lane = tid & 31;
    const int warp = tid >> 5;
    const int row0 = blockIdx.x * RPB;

    // stage 32 input rows (1024 float4; 8 per thread)
    #pragma unroll
    for (int i = 0; i < 8; i++) {
        const int idx   = tid + i * 128;
        const int row   = idx >> 5;
        const int chunk = idx & 31;
        int grow = row0 + row;
        if (grow >= NN) grow = NN - 1;         // clamp (tail block)
        ((float4*)&s_in[row][0])[chunk] =
            ((const float4*)(inp + (size_t)grow * F))[chunk];
    }
    __syncthreads();

    ull acc[8][4];
    #pragma unroll
    for (int r = 0; r < 8; r++)
        #pragma unroll
        for (int i = 0; i < 4; i++)
            acc[r][i] = 0ULL;

    const int colbase = lane * 4;
    const int rbase   = warp * 8;

    #pragma unroll 4
    for (int k = 0; k < F; k += 2) {
        const float4 wa = *(const float4*)(W + (size_t)k * F + colbase);
        const float4 wb = *(const float4*)(W + (size_t)(k + 1) * F + colbase);
        const ull wp0 = pack2(wa.x, wb.x);
        const ull wp1 = pack2(wa.y, wb.y);
        const ull wp2 = pack2(wa.z, wb.z);
        const ull wp3 = pack2(wa.w, wb.w);
        #pragma unroll
        for (int r = 0; r < 8; r++) {
            const ull ip = *(const ull*)&s_in[rbase + r][k];  // == pack2(s[k],s[k+1])
            ffma2(acc[r][0], ip, wp0);
            ffma2(acc[r][1], ip, wp1);
            ffma2(acc[r][2], ip, wp2);
            ffma2(acc[r][3], ip, wp3);
        }
    }

    #pragma unroll
    for (int r = 0; r < 8; r++) {
        const int row = row0 + rbase + r;
        if (row >= NN) continue;
        float4 hv;
        float lo, hi;
        unpack2(acc[r][0], lo, hi); hv.x = lo + hi;
        unpack2(acc[r][1], lo, hi); hv.y = lo + hi;
        unpack2(acc[r][2], lo, hi); hv.z = lo + hi;
        unpack2(acc[r][3], lo, hi); hv.w = lo + hi;
        *(float4*)(g_h + (size_t)row * F + colbase) = hv;
    }
}

// ============================================================================
// Kernel A2: hc dots, fp64 — ONE THREAD per (row, vec), in-thread binary tree.
// CONTRACT (validated bitwise in R11 vs the shfl version):
//   p_j = h[4j]*c[4j] + h[4j+1]*c[4j+1] + h[4j+2]*c[4j+2] + h[4j+3]*c[4j+3]
//   (left-to-right fp64), then p[j] += p[j+off] for off = 16,8,4,2,1 -> p[0].
// block = 256: threads 0..127 -> c1 rows base..base+127,
//              threads 128..255 -> c2 same rows.
// ============================================================================
__global__ void __launch_bounds__(256) hc_kernel(
    const float* __restrict__ c1,
    const float* __restrict__ c2)
{
    const int tid  = threadIdx.x;
    const int row  = blockIdx.x * 128 + (tid & 127);
    const bool is2 = tid >= 128;
    if (row >= NN) return;

    const float* cvec = is2 ? c2 : c1;
    const float* hrow = g_h + (size_t)row * F;

    double p[32];
    #pragma unroll
    for (int j = 0; j < 32; j++) {
        const float4 hv = ((const float4*)hrow)[j];
        const float4 cc = ((const float4*)cvec)[j];
        p[j] = (double)hv.x * (double)cc.x + (double)hv.y * (double)cc.y
             + (double)hv.z * (double)cc.z + (double)hv.w * (double)cc.w;
    }
    #pragma unroll
    for (int off = 16; off >= 1; off >>= 1)
        #pragma unroll
        for (int j = 0; j < off; j++)
            p[j] += p[j + off];

    if (is2) g_hc2[row] = (float)p[0];
    else     g_hc1[row] = (float)p[0];
}

// ============================================================================
// Kernel B: per-node attention (frozen since R6).
// ============================================================================
__global__ void __launch_bounds__(256) attn_kernel(
    const int* __restrict__ adj,
    const int* __restrict__ deg,
    float* __restrict__ out)
{
    __shared__ float s_buf[8][KNBR];

    const unsigned FULL = 0xffffffffu;
    const int warp = threadIdx.x >> 5;
    const int lane = threadIdx.x & 31;
    const int m    = blockIdx.x * 8 + warp;   // 6250 * 8 == 50000 exactly

    const int  d     = deg[m];
    const int  a     = adj[(size_t)m * KNBR + lane];
    const bool valid = (lane < d);

    const float NEG_INF = __int_as_float(0xff800000u);

    float e32 = NEG_INF;
    if (valid) {
        const float x = g_hc1[m] + g_hc2[a];   // fp32 add, as reference
        e32 = (x >= 0.f) ? x : 0.2f * x;
    }

    float mx = e32;
    #pragma unroll
    for (int off = 16; off > 0; off >>= 1)
        mx = fmaxf(mx, __shfl_xor_sync(FULL, mx, off));

    const float p = valid ? expf(e32 - mx) : 0.f;

    // ---- pass 1: sequential fp32 sum of p ----
    s_buf[warp][lane] = p;
    __syncwarp();
    float s = 0.f;
    #pragma unroll
    for (int q = 0; q < 8; q++) {
        const float4 v = *(const float4*)&s_buf[warp][q * 4];
        s += v.x; s += v.y; s += v.z; s += v.w;
    }

    const float att = p / s;

    // ---- pass 2: sequential fp32 prefix sum with capture-at-index ----
    __syncwarp();
    s_buf[warp][lane] = att;
    __syncwarp();
    float run = 0.f, csum = 0.f, shifted = 0.f;
    const int lm3 = lane - WSIZE;
    #pragma unroll
    for (int q = 0; q < 8; q++) {
        const float4 v = *(const float4*)&s_buf[warp][q * 4];
        const int k0 = q * 4;
        run += v.x; if (k0 + 0 == lane) csum = run; if (k0 + 0 == lm3) shifted = run;
        run += v.y; if (k0 + 1 == lane) csum = run; if (k0 + 1 == lm3) shifted = run;
        run += v.z; if (k0 + 2 == lane) csum = run; if (k0 + 2 == lm3) shifted = run;
        run += v.w; if (k0 + 3 == lane) csum = run; if (k0 + 3 == lm3) shifted = run;
    }

    float win = -1.0f;
    if (lane >= WSIZE - 1 && lane < d)
        win = csum - shifted;

    // argmax, first occurrence on ties
    float bw = win;
    int   bj = lane;
    #pragma unroll
    for (int off = 16; off > 0; off >>= 1) {
        const float ow = __shfl_down_sync(FULL, bw, off);
        const int   oj = __shfl_down_sync(FULL, bj, off);
        if (ow > bw || (ow == bw && oj < bj)) { bw = ow; bj = oj; }
    }
    const int jstar = __shfl_sync(FULL, bj, 0);

    const float scale = (float)d / 3.0f;
    const float t = (lane >= jstar - (WSIZE - 1) && lane <= jstar) ? att * scale : 0.f;

    const float w0 = __shfl_sync(FULL, t, jstar - 2);
    const float w1 = __shfl_sync(FULL, t, jstar - 1);
    const float w2 = __shfl_sync(FULL, t, jstar);
    const int   a0 = __shfl_sync(FULL, a, jstar - 2);
    const int   a1 = __shfl_sync(FULL, a, jstar - 1);
    const int   a2 = __shfl_sync(FULL, a, jstar);

    const float4 v0 = ((const float4*)(g_h + (size_t)a0 * F))[lane];
    const float4 v1 = ((const float4*)(g_h + (size_t)a1 * F))[lane];
    const float4 v2 = ((const float4*)(g_h + (size_t)a2 * F))[lane];

    float4 o;
    o.x = fmaf(w2, v2.x, fmaf(w1, v1.x, w0 * v0.x));
    o.y = fmaf(w2, v2.y, fmaf(w1, v1.y, w0 * v0.y));
    o.z = fmaf(w2, v2.z, fmaf(w1, v1.z, w0 * v0.z));
    o.w = fmaf(w2, v2.w, fmaf(w1, v1.w, w0 * v0.w));

    o.x = (o.x > 0.f) ? o.x : expm1f(o.x);
    o.y = (o.y > 0.f) ? o.y : expm1f(o.y);
    o.z = (o.z > 0.f) ? o.z : expm1f(o.z);
    o.w = (o.w > 0.f) ? o.w : expm1f(o.w);

    ((float4*)out)[(size_t)m * (F / 4) + lane] = o;
}

extern "C" void kernel_launch(void* const* d_in, const int* in_sizes, int n_in,
                              void* d_out, int out_size) {
    const float* inp = (const float*)d_in[0];
    const float* W   = (const float*)d_in[1];
    const float* c1  = (const float*)d_in[2];
    const float* c2  = (const float*)d_in[3];
    const int*   adj = (const int*)d_in[4];
    const int*   deg = (const int*)d_in[5];
    float*       out = (float*)d_out;

    gemm_kernel<<<(NN + RPB - 1) / RPB, 128>>>(inp, W);     // 1563 blocks
    hc_kernel<<<(NN + 127) / 128, 256>>>(c1, c2);           // 391 blocks
    attn_kernel<<<NN / 8, 256>>>(adj, deg, out);            // 6250 blocks
}

// round 13
// speedup vs baseline: 1.9048x; 1.9048x over previous
#include <cuda_runtime.h>
#include <math.h>

#define NN 50000          // N_NODES == M_NODES
#define KNBR 32
#define F 128
#define WSIZE 3
#define RPB 32            // rows per block (4 warps x 8 rows)

typedef unsigned long long ull;

// Scratch (device globals: allocation-free per harness rules)
__device__ float g_h[(size_t)NN * F];     // h = input @ W  (fp32)
__device__ float g_hc1[NN];               // compensated-fp32 h . c1 (== fl32(exact))
__device__ float g_hc2[NN];               // compensated-fp32 h . c2
__device__ ull   g_Wp[64 * F];            // W pre-packed: (W[2kp][c], W[2kp+1][c])

// ---- packed f32x2 helpers ----
static __device__ __forceinline__ ull pack2(float lo, float hi) {
    ull r;
    asm("mov.b64 %0, {%1, %2};" : "=l"(r) : "f"(lo), "f"(hi));
    return r;
}
static __device__ __forceinline__ void unpack2(ull v, float& lo, float& hi) {
    asm("mov.b64 {%0, %1}, %2;" : "=f"(lo), "=f"(hi) : "l"(v));
}
static __device__ __forceinline__ void ffma2(ull& d, ull a, ull b) {
    asm("fma.rn.f32x2 %0, %1, %2, %0;" : "+l"(d) : "l"(a), "l"(b));
}

// ---- error-free fp32 transforms (Dot2 building blocks) ----
static __device__ __forceinline__ void twoprod(float a, float b, float& p, float& e) {
    p = a * b;
    e = fmaf(a, b, -p);
}
static __device__ __forceinline__ void twosum(float a, float b, float& s, float& err) {
    s = a + b;
    const float z = s - a;
    err = (a - (s - z)) + (b - z);
}

// ============================================================================
// Kernel 0: pre-pack W into even/odd-k f32x2 pairs (64 KB total).
// g_Wp[kp*128 + c] = (W[2kp][c], W[2kp+1][c])
// ============================================================================
__global__ void pack_w_kernel(const float* __restrict__ W)
{
    const int i = blockIdx.x * blockDim.x + threadIdx.x;   // 0..8191
    const int kp  = i >> 7;
    const int col = i & 127;
    g_Wp[i] = pack2(W[(2 * kp) * F + col], W[(2 * kp + 1) * F + col]);
}

// ============================================================================
// Kernel A: h = input @ W — pure GEMM, pre-packed W (zero pack MOVs).
// ARITHMETIC CONTRACT (bitwise, frozen): for each (row, col),
//   acc.lo = sum over even k ascending of in[k]*W[k][c]
//   acc.hi = sum over odd  k ascending;  h = acc.lo + acc.hi
// FFMA2 operands/order identical to R10/R12 (g_Wp pair == pack2(wa, wb)).
// block = 128 threads (4 warps), 32 rows/block, 8 rows/warp, 4 cols/lane.
// ============================================================================
__global__ void __launch_bounds__(128) gemm_kernel(
    const float* __restrict__ inp)
{
    __shared__ float s_in[RPB][F];   // 16 KB

    const int tid  = threadIdx.x;
    const int lane = tid & 31;
    const int warp = tid >> 5;
    const int row0 = blockIdx.x * RPB;

    // stage 32 input rows (1024 float4; 8 per thread)
    #pragma unroll
    for (int i = 0; i < 8; i++) {
        const int idx   = tid + i * 128;
        const int row   = idx >> 5;
        const int chunk = idx & 31;
        int grow = row0 + row;
        if (grow >= NN) grow = NN - 1;         // clamp (tail block)
        ((float4*)&s_in[row][0])[chunk] =
            ((const float4*)(inp + (size_t)grow * F))[chunk];
    }
    __syncthreads();

    ull acc[8][4];
    #pragma unroll
    for (int r = 0; r < 8; r++)
        #pragma unroll
        for (int i = 0; i < 4; i++)
            acc[r][i] = 0ULL;

    const int colbase = lane * 4;
    const int rbase   = warp * 8;

    #pragma unroll 4
    for (int kp = 0; kp < 64; kp++) {          // k = 2*kp, 2*kp+1
        const ulonglong2 w01 = *(const ulonglong2*)(g_Wp + kp * F + colbase);
        const ulonglong2 w23 = *(const ulonglong2*)(g_Wp + kp * F + colbase + 2);
        #pragma unroll
        for (int r = 0; r < 8; r++) {
            const ull ip = *(const ull*)&s_in[rbase + r][kp * 2];  // (s[k], s[k+1])
            ffma2(acc[r][0], ip, w01.x);
            ffma2(acc[r][1], ip, w01.y);
            ffma2(acc[r][2], ip, w23.x);
            ffma2(acc[r][3], ip, w23.y);
        }
    }

    #pragma unroll
    for (int r = 0; r < 8; r++) {
        const int row = row0 + rbase + r;
        if (row >= NN) continue;
        float4 hv;
        float lo, hi;
        unpack2(acc[r][0], lo, hi); hv.x = lo + hi;
        unpack2(acc[r][1], lo, hi); hv.y = lo + hi;
        unpack2(acc[r][2], lo, hi); hv.z = lo + hi;
        unpack2(acc[r][3], lo, hi); hv.w = lo + hi;
        *(float4*)(g_h + (size_t)row * F + colbase) = hv;
    }
}

// ============================================================================
// Kernel A2: hc dots — compensated fp32 (Dot2), ZERO fp64.
// Result == fl32(exact dot) except ~2^-17-probability 1-ulp boundary cases
// (same tolerance class as R6's validated e perturbations).
// block 256 = 8 warps: warps 0-3 -> c1 rows [base..base+32),
//                      warps 4-7 -> c2 same rows. Lane owns cols lane*4..+3.
// ============================================================================
__global__ void __launch_bounds__(256) hc_kernel(
    const float* __restrict__ c1,
    const float* __restrict__ c2)
{
    const unsigned FULL = 0xffffffffu;
    const int warp = threadIdx.x >> 5;
    const int lane = threadIdx.x & 31;
    const bool is2 = warp >= 4;
    const int rowbase = blockIdx.x * 32 + (warp & 3) * 8;
    const int colbase = lane * 4;

    const float* cvec = is2 ? c2 : c1;
    const float4 cc = *(const float4*)(cvec + colbase);

    #pragma unroll
    for (int r = 0; r < 8; r++) {
        const int row = rowbase + r;
        if (row >= NN) break;
        const float4 hv = *(const float4*)(g_h + (size_t)row * F + colbase);

        // local Dot2 over the lane's 4 products
        float s, c, p, e, err;
        twoprod(hv.x, cc.x, s, c);
        twoprod(hv.y, cc.y, p, e);
        twosum(s, p, s, err); c += err + e;
        twoprod(hv.z, cc.z, p, e);
        twosum(s, p, s, err); c += err + e;
        twoprod(hv.w, cc.w, p, e);
        twosum(s, p, s, err); c += err + e;

        // cross-lane df reduction (fp32 shfls)
        #pragma unroll
        for (int off = 16; off > 0; off >>= 1) {
            const float s2 = __shfl_down_sync(FULL, s, off);
            const float c2v = __shfl_down_sync(FULL, c, off);
            twosum(s, s2, s, err);
            c += err + c2v;
        }
        if (lane == 0) {
            const float res = s + c;
            if (is2) g_hc2[row] = res;
            else     g_hc1[row] = res;
        }
    }
}

// ============================================================================
// Kernel B: per-node attention (frozen since R6).
// ============================================================================
__global__ void __launch_bounds__(256) attn_kernel(
    const int* __restrict__ adj,
    const int* __restrict__ deg,
    float* __restrict__ out)
{
    __shared__ float s_buf[8][KNBR];

    const unsigned FULL = 0xffffffffu;
    const int warp = threadIdx.x >> 5;
    const int lane = threadIdx.x & 31;
    const int m    = blockIdx.x * 8 + warp;   // 6250 * 8 == 50000 exactly

    const int  d     = deg[m];
    const int  a     = adj[(size_t)m * KNBR + lane];
    const bool valid = (lane < d);

    const float NEG_INF = __int_as_float(0xff800000u);

    float e32 = NEG_INF;
    if (valid) {
        const float x = g_hc1[m] + g_hc2[a];   // fp32 add, as reference
        e32 = (x >= 0.f) ? x : 0.2f * x;
    }

    float mx = e32;
    #pragma unroll
    for (int off = 16; off > 0; off >>= 1)
        mx = fmaxf(mx, __shfl_xor_sync(FULL, mx, off));

    const float p = valid ? expf(e32 - mx) : 0.f;

    // ---- pass 1: sequential fp32 sum of p ----
    s_buf[warp][lane] = p;
    __syncwarp();
    float s = 0.f;
    #pragma unroll
    for (int q = 0; q < 8; q++) {
        const float4 v = *(const float4*)&s_buf[warp][q * 4];
        s += v.x; s += v.y; s += v.z; s += v.w;
    }

    const float att = p / s;

    // ---- pass 2: sequential fp32 prefix sum with capture-at-index ----
    __syncwarp();
    s_buf[warp][lane] = att;
    __syncwarp();
    float run = 0.f, csum = 0.f, shifted = 0.f;
    const int lm3 = lane - WSIZE;
    #pragma unroll
    for (int q = 0; q < 8; q++) {
        const float4 v = *(const float4*)&s_buf[warp][q * 4];
        const int k0 = q * 4;
        run += v.x; if (k0 + 0 == lane) csum = run; if (k0 + 0 == lm3) shifted = run;
        run += v.y; if (k0 + 1 == lane) csum = run; if (k0 + 1 == lm3) shifted = run;
        run += v.z; if (k0 + 2 == lane) csum = run; if (k0 + 2 == lm3) shifted = run;
        run += v.w; if (k0 + 3 == lane) csum = run; if (k0 + 3 == lm3) shifted = run;
    }

    float win = -1.0f;
    if (lane >= WSIZE - 1 && lane < d)
        win = csum - shifted;

    // argmax, first occurrence on ties
    float bw = win;
    int   bj = lane;
    #pragma unroll
    for (int off = 16; off > 0; off >>= 1) {
        const float ow = __shfl_down_sync(FULL, bw, off);
        const int   oj = __shfl_down_sync(FULL, bj, off);
        if (ow > bw || (ow == bw && oj < bj)) { bw = ow; bj = oj; }
    }
    const int jstar = __shfl_sync(FULL, bj, 0);

    const float scale = (float)d / 3.0f;
    const float t = (lane >= jstar - (WSIZE - 1) && lane <= jstar) ? att * scale : 0.f;

    const float w0 = __shfl_sync(FULL, t, jstar - 2);
    const float w1 = __shfl_sync(FULL, t, jstar - 1);
    const float w2 = __shfl_sync(FULL, t, jstar);
    const int   a0 = __shfl_sync(FULL, a, jstar - 2);
    const int   a1 = __shfl_sync(FULL, a, jstar - 1);
    const int   a2 = __shfl_sync(FULL, a, jstar);

    const float4 v0 = ((const float4*)(g_h + (size_t)a0 * F))[lane];
    const float4 v1 = ((const float4*)(g_h + (size_t)a1 * F))[lane];
    const float4 v2 = ((const float4*)(g_h + (size_t)a2 * F))[lane];

    float4 o;
    o.x = fmaf(w2, v2.x, fmaf(w1, v1.x, w0 * v0.x));
    o.y = fmaf(w2, v2.y, fmaf(w1, v1.y, w0 * v0.y));
    o.z = fmaf(w2, v2.z, fmaf(w1, v1.z, w0 * v0.z));
    o.w = fmaf(w2, v2.w, fmaf(w1, v1.w, w0 * v0.w));

    o.x = (o.x > 0.f) ? o.x : expm1f(o.x);
    o.y = (o.y > 0.f) ? o.y : expm1f(o.y);
    o.z = (o.z > 0.f) ? o.z : expm1f(o.z);
    o.w = (o.w > 0.f) ? o.w : expm1f(o.w);

    ((float4*)out)[(size_t)m * (F / 4) + lane] = o;
}

extern "C" void kernel_launch(void* const* d_in, const int* in_sizes, int n_in,
                              void* d_out, int out_size) {
    const float* inp = (const float*)d_in[0];
    const float* W   = (const float*)d_in[1];
    const float* c1  = (const float*)d_in[2];
    const float* c2  = (const float*)d_in[3];
    const int*   adj = (const int*)d_in[4];
    const int*   deg = (const int*)d_in[5];
    float*       out = (float*)d_out;

    pack_w_kernel<<<32, 256>>>(W);                          // 8192 threads
    gemm_kernel<<<(NN + RPB - 1) / RPB, 128>>>(inp);        // 1563 blocks
    hc_kernel<<<(NN + 31) / 32, 256>>>(c1, c2);             // 1563 blocks
    attn_kernel<<<NN / 8, 256>>>(adj, deg, out);            // 6250 blocks
}

// round 14
// speedup vs baseline: 1.9386x; 1.0177x over previous
#include <cuda_runtime.h>
#include <math.h>

#define NN 50000          // N_NODES == M_NODES
#define KNBR 32
#define F 128
#define WSIZE 3
#define RPB 32            // rows per block (4 row-groups x 8 rows)

typedef unsigned long long ull;

// Scratch (device globals: allocation-free per harness rules)
__device__ float g_h[(size_t)NN * F];     // h = input @ W  (fp32)
__device__ float g_hc1[NN];               // compensated-fp32 h . c1 (== fl32(exact))
__device__ float g_hc2[NN];               // compensated-fp32 h . c2
__device__ ull   g_Wp[64 * F];            // W pre-packed: (W[2kp][c], W[2kp+1][c])

// ---- packed f32x2 helpers ----
static __device__ __forceinline__ ull pack2(float lo, float hi) {
    ull r;
    asm("mov.b64 %0, {%1, %2};" : "=l"(r) : "f"(lo), "f"(hi));
    return r;
}
static __device__ __forceinline__ void unpack2(ull v, float& lo, float& hi) {
    asm("mov.b64 {%0, %1}, %2;" : "=f"(lo), "=f"(hi) : "l"(v));
}
static __device__ __forceinline__ void ffma2(ull& d, ull a, ull b) {
    asm("fma.rn.f32x2 %0, %1, %2, %0;" : "+l"(d) : "l"(a), "l"(b));
}

// ---- error-free fp32 transforms (Dot2 building blocks) ----
static __device__ __forceinline__ void twoprod(float a, float b, float& p, float& e) {
    p = a * b;
    e = fmaf(a, b, -p);
}
static __device__ __forceinline__ void twosum(float a, float b, float& s, float& err) {
    s = a + b;
    const float z = s - a;
    err = (a - (s - z)) + (b - z);
}

// ============================================================================
// Kernel 0: pre-pack W into even/odd-k f32x2 pairs (64 KB total).
// g_Wp[kp*128 + c] = (W[2kp][c], W[2kp+1][c])
// ============================================================================
__global__ void pack_w_kernel(const float* __restrict__ W)
{
    const int i = blockIdx.x * blockDim.x + threadIdx.x;   // 0..8191
    const int kp  = i >> 7;
    const int col = i & 127;
    g_Wp[i] = pack2(W[(2 * kp) * F + col], W[(2 * kp + 1) * F + col]);
}

// ============================================================================
// Kernel A: h = input @ W — pure GEMM, pre-packed W, COLUMN-SPLIT for occupancy.
// ARITHMETIC CONTRACT (bitwise, frozen): for each (row, col),
//   acc.lo = sum over even k ascending of in[k]*W[k][c]
//   acc.hi = sum over odd  k ascending;  h = acc.lo + acc.hi
// Identical FFMA2 operands/order to R13; only the (warp,lane)->cols map
// changed: 8 warps/block = 4 row-groups x 2 col-halves; lane owns 2 cols.
// acc[8][2] = 32 regs (was 64) -> 3-4x occupancy.
// ============================================================================
__global__ void __launch_bounds__(256) gemm_kernel(
    const float* __restrict__ inp)
{
    __shared__ float s_in[RPB][F];   // 16 KB

    const int tid  = threadIdx.x;
    const int lane = tid & 31;
    const int warp = tid >> 5;
    const int row0 = blockIdx.x * RPB;

    // stage 32 input rows (1024 float4; 4 per thread)
    #pragma unroll
    for (int i = 0; i < 4; i++) {
        const int idx   = tid + i * 256;
        const int row   = idx >> 5;
        const int chunk = idx & 31;
        int grow = row0 + row;
        if (grow >= NN) grow = NN - 1;         // clamp (tail block)
        ((float4*)&s_in[row][0])[chunk] =
            ((const float4*)(inp + (size_t)grow * F))[chunk];
    }
    __syncthreads();

    ull acc[8][2];
    #pragma unroll
    for (int r = 0; r < 8; r++) { acc[r][0] = 0ULL; acc[r][1] = 0ULL; }

    const int colbase = (warp & 1) * 64 + lane * 2;   // 2 cols per lane
    const int rbase   = (warp >> 1) * 8;              // 8 rows per warp

    #pragma unroll 4
    for (int kp = 0; kp < 64; kp++) {          // k = 2*kp, 2*kp+1
        const ulonglong2 wv = *(const ulonglong2*)(g_Wp + kp * F + colbase);
        #pragma unroll
        for (int r = 0; r < 8; r++) {
            const ull ip = *(const ull*)&s_in[rbase + r][kp * 2];  // (s[k], s[k+1])
            ffma2(acc[r][0], ip, wv.x);
            ffma2(acc[r][1], ip, wv.y);
        }
    }

    #pragma unroll
    for (int r = 0; r < 8; r++) {
        const int row = row0 + rbase + r;
        if (row >= NN) continue;
        float2 hv;
        float lo, hi;
        unpack2(acc[r][0], lo, hi); hv.x = lo + hi;
        unpack2(acc[r][1], lo, hi); hv.y = lo + hi;
        *(float2*)(g_h + (size_t)row * F + colbase) = hv;
    }
}

// ============================================================================
// Kernel A2: hc dots — compensated fp32 (Dot2), ZERO fp64 (validated R13).
// block 256 = 8 warps: warps 0-3 -> c1 rows [base..base+32),
//                      warps 4-7 -> c2 same rows. Lane owns cols lane*4..+3.
// ============================================================================
__global__ void __launch_bounds__(256) hc_kernel(
    const float* __restrict__ c1,
    const float* __restrict__ c2)
{
    const unsigned FULL = 0xffffffffu;
    const int warp = threadIdx.x >> 5;
    const int lane = threadIdx.x & 31;
    const bool is2 = warp >= 4;
    const int rowbase = blockIdx.x * 32 + (warp & 3) * 8;
    const int colbase = lane * 4;

    const float* cvec = is2 ? c2 : c1;
    const float4 cc = *(const float4*)(cvec + colbase);

    #pragma unroll
    for (int r = 0; r < 8; r++) {
        const int row = rowbase + r;
        if (row >= NN) break;
        const float4 hv = *(const float4*)(g_h + (size_t)row * F + colbase);

        // local Dot2 over the lane's 4 products
        float s, c, p, e, err;
        twoprod(hv.x, cc.x, s, c);
        twoprod(hv.y, cc.y, p, e);
        twosum(s, p, s, err); c += err + e;
        twoprod(hv.z, cc.z, p, e);
        twosum(s, p, s, err); c += err + e;
        twoprod(hv.w, cc.w, p, e);
        twosum(s, p, s, err); c += err + e;

        // cross-lane df reduction (fp32 shfls)
        #pragma unroll
        for (int off = 16; off > 0; off >>= 1) {
            const float s2 = __shfl_down_sync(FULL, s, off);
            const float c2v = __shfl_down_sync(FULL, c, off);
            twosum(s, s2, s, err);
            c += err + c2v;
        }
        if (lane == 0) {
            const float res = s + c;
            if (is2) g_hc2[row] = res;
            else     g_hc1[row] = res;
        }
    }
}

// ============================================================================
// Kernel B: per-node attention (frozen since R6).
// ============================================================================
__global__ void __launch_bounds__(256) attn_kernel(
    const int* __restrict__ adj,
    const int* __restrict__ deg,
    float* __restrict__ out)
{
    __shared__ float s_buf[8][KNBR];

    const unsigned FULL = 0xffffffffu;
    const int warp = threadIdx.x >> 5;
    const int lane = threadIdx.x & 31;
    const int m    = blockIdx.x * 8 + warp;   // 6250 * 8 == 50000 exactly

    const int  d     = deg[m];
    const int  a     = adj[(size_t)m * KNBR + lane];
    const bool valid = (lane < d);

    const float NEG_INF = __int_as_float(0xff800000u);

    float e32 = NEG_INF;
    if (valid) {
        const float x = g_hc1[m] + g_hc2[a];   // fp32 add, as reference
        e32 = (x >= 0.f) ? x : 0.2f * x;
    }

    float mx = e32;
    #pragma unroll
    for (int off = 16; off > 0; off >>= 1)
        mx = fmaxf(mx, __shfl_xor_sync(FULL, mx, off));

    const float p = valid ? expf(e32 - mx) : 0.f;

    // ---- pass 1: sequential fp32 sum of p ----
    s_buf[warp][lane] = p;
    __syncwarp();
    float s = 0.f;
    #pragma unroll
    for (int q = 0; q < 8; q++) {
        const float4 v = *(const float4*)&s_buf[warp][q * 4];
        s += v.x; s += v.y; s += v.z; s += v.w;
    }

    const float att = p / s;

    // ---- pass 2: sequential fp32 prefix sum with capture-at-index ----
    __syncwarp();
    s_buf[warp][lane] = att;
    __syncwarp();
    float run = 0.f, csum = 0.f, shifted = 0.f;
    const int lm3 = lane - WSIZE;
    #pragma unroll
    for (int q = 0; q < 8; q++) {
        const float4 v = *(const float4*)&s_buf[warp][q * 4];
        const int k0 = q * 4;
        run += v.x; if (k0 + 0 == lane) csum = run; if (k0 + 0 == lm3) shifted = run;
        run += v.y; if (k0 + 1 == lane) csum = run; if (k0 + 1 == lm3) shifted = run;
        run += v.z; if (k0 + 2 == lane) csum = run; if (k0 + 2 == lm3) shifted = run;
        run += v.w; if (k0 + 3 == lane) csum = run; if (k0 + 3 == lm3) shifted = run;
    }

    float win = -1.0f;
    if (lane >= WSIZE - 1 && lane < d)
        win = csum - shifted;

    // argmax, first occurrence on ties
    float bw = win;
    int   bj = lane;
    #pragma unroll
    for (int off = 16; off > 0; off >>= 1) {
        const float ow = __shfl_down_sync(FULL, bw, off);
        const int   oj = __shfl_down_sync(FULL, bj, off);
        if (ow > bw || (ow == bw && oj < bj)) { bw = ow; bj = oj; }
    }
    const int jstar = __shfl_sync(FULL, bj, 0);

    const float scale = (float)d / 3.0f;
    const float t = (lane >= jstar - (WSIZE - 1) && lane <= jstar) ? att * scale : 0.f;

    const float w0 = __shfl_sync(FULL, t, jstar - 2);
    const float w1 = __shfl_sync(FULL, t, jstar - 1);
    const float w2 = __shfl_sync(FULL, t, jstar);
    const int   a0 = __shfl_sync(FULL, a, jstar - 2);
    const int   a1 = __shfl_sync(FULL, a, jstar - 1);
    const int   a2 = __shfl_sync(FULL, a, jstar);

    const float4 v0 = ((const float4*)(g_h + (size_t)a0 * F))[lane];
    const float4 v1 = ((const float4*)(g_h + (size_t)a1 * F))[lane];
    const float4 v2 = ((const float4*)(g_h + (size_t)a2 * F))[lane];

    float4 o;
    o.x = fmaf(w2, v2.x, fmaf(w1, v1.x, w0 * v0.x));
    o.y = fmaf(w2, v2.y, fmaf(w1, v1.y, w0 * v0.y));
    o.z = fmaf(w2, v2.z, fmaf(w1, v1.z, w0 * v0.z));
    o.w = fmaf(w2, v2.w, fmaf(w1, v1.w, w0 * v0.w));

    o.x = (o.x > 0.f) ? o.x : expm1f(o.x);
    o.y = (o.y > 0.f) ? o.y : expm1f(o.y);
    o.z = (o.z > 0.f) ? o.z : expm1f(o.z);
    o.w = (o.w > 0.f) ? o.w : expm1f(o.w);

    ((float4*)out)[(size_t)m * (F / 4) + lane] = o;
}

extern "C" void kernel_launch(void* const* d_in, const int* in_sizes, int n_in,
                              void* d_out, int out_size) {
    const float* inp = (const float*)d_in[0];
    const float* W   = (const float*)d_in[1];
    const float* c1  = (const float*)d_in[2];
    const float* c2  = (const float*)d_in[3];
    const int*   adj = (const int*)d_in[4];
    const int*   deg = (const int*)d_in[5];
    float*       out = (float*)d_out;

    pack_w_kernel<<<32, 256>>>(W);                          // 8192 threads
    gemm_kernel<<<(NN + RPB - 1) / RPB, 256>>>(inp);        // 1563 blocks
    hc_kernel<<<(NN + 31) / 32, 256>>>(c1, c2);             // 1563 blocks
    attn_kernel<<<NN / 8, 256>>>(adj, deg, out);            // 6250 blocks
}

// round 15
// speedup vs baseline: 2.0151x; 1.0395x over previous
#include <cuda_runtime.h>
#include <math.h>

#define NN 50000          // N_NODES == M_NODES
#define KNBR 32
#define F 128
#define WSIZE 3
#define RPB 32            // rows per block (4 row-groups x 8 rows)

typedef unsigned long long ull;

// Scratch (device globals: allocation-free per harness rules)
__device__ float g_h[(size_t)NN * F];     // h = input @ W  (fp32)
__device__ float g_hc1[NN];               // compensated-fp32 h . c1 (== fl32(exact))
__device__ float g_hc2[NN];               // compensated-fp32 h . c2
__device__ ull   g_Wp[64 * F];            // W pre-packed: (W[2kp][c], W[2kp+1][c])

// ---- packed f32x2 helpers ----
static __device__ __forceinline__ ull pack2(float lo, float hi) {
    ull r;
    asm("mov.b64 %0, {%1, %2};" : "=l"(r) : "f"(lo), "f"(hi));
    return r;
}
static __device__ __forceinline__ void unpack2(ull v, float& lo, float& hi) {
    asm("mov.b64 {%0, %1}, %2;" : "=f"(lo), "=f"(hi) : "l"(v));
}
static __device__ __forceinline__ void ffma2(ull& d, ull a, ull b) {
    asm("fma.rn.f32x2 %0, %1, %2, %0;" : "+l"(d) : "l"(a), "l"(b));
}

// ---- error-free fp32 transforms (Dot2 building blocks) ----
static __device__ __forceinline__ void twoprod(float a, float b, float& p, float& e) {
    p = a * b;
    e = fmaf(a, b, -p);
}
static __device__ __forceinline__ void twosum(float a, float b, float& s, float& err) {
    s = a + b;
    const float z = s - a;
    err = (a - (s - z)) + (b - z);
}

// ============================================================================
// Kernel 0: pre-pack W into even/odd-k f32x2 pairs (64 KB total).
// g_Wp[kp*128 + c] = (W[2kp][c], W[2kp+1][c])
// ============================================================================
__global__ void pack_w_kernel(const float* __restrict__ W)
{
    const int i = blockIdx.x * blockDim.x + threadIdx.x;   // 0..8191
    const int kp  = i >> 7;
    const int col = i & 127;
    g_Wp[i] = pack2(W[(2 * kp) * F + col], W[(2 * kp + 1) * F + col]);
}

// ============================================================================
// Kernel A: h = input @ W — pre-packed W, column-split, LDS.128 input loads
// (2 kp-pairs per shared load -> half the crossbar traffic of R14).
// ARITHMETIC CONTRACT (bitwise, frozen): for each (row, col),
//   acc.lo = sum over even k ascending of in[k]*W[k][c]
//   acc.hi = sum over odd  k ascending;  h = acc.lo + acc.hi
// Per-acc FFMA2 order remains ascending kp (kp then kp+1 inside each step).
// 8 warps/block = 4 row-groups x 2 col-halves; lane owns 2 cols; acc = 32 regs.
// ============================================================================
__global__ void __launch_bounds__(256) gemm_kernel(
    const float* __restrict__ inp)
{
    __shared__ float s_in[RPB][F];   // 16 KB

    const int tid  = threadIdx.x;
    const int lane = tid & 31;
    const int warp = tid >> 5;
    const int row0 = blockIdx.x * RPB;

    // stage 32 input rows (1024 float4; 4 per thread)
    #pragma unroll
    for (int i = 0; i < 4; i++) {
        const int idx   = tid + i * 256;
        const int row   = idx >> 5;
        const int chunk = idx & 31;
        int grow = row0 + row;
        if (grow >= NN) grow = NN - 1;         // clamp (tail block)
        ((float4*)&s_in[row][0])[chunk] =
            ((const float4*)(inp + (size_t)grow * F))[chunk];
    }
    __syncthreads();

    ull acc[8][2];
    #pragma unroll
    for (int r = 0; r < 8; r++) { acc[r][0] = 0ULL; acc[r][1] = 0ULL; }

    const int colbase = (warp & 1) * 64 + lane * 2;   // 2 cols per lane
    const int rbase   = (warp >> 1) * 8;              // 8 rows per warp

    #pragma unroll 4
    for (int kp = 0; kp < 64; kp += 2) {       // two kp-pairs per step
        // W pairs for kp and kp+1 at this lane's 2 cols
        const ulonglong2 wA = *(const ulonglong2*)(g_Wp + kp * F + colbase);
        const ulonglong2 wB = *(const ulonglong2*)(g_Wp + (kp + 1) * F + colbase);
        #pragma unroll
        for (int r = 0; r < 8; r++) {
            // one LDS.128: (s[k],s[k+1]) and (s[k+2],s[k+3]) — bit-equal to
            // the two pack2() pairs of R14
            const ulonglong2 ipq = *(const ulonglong2*)&s_in[rbase + r][kp * 2];
            ffma2(acc[r][0], ipq.x, wA.x);   // kp    , col 0
            ffma2(acc[r][0], ipq.y, wB.x);   // kp + 1, col 0
            ffma2(acc[r][1], ipq.x, wA.y);   // kp    , col 1
            ffma2(acc[r][1], ipq.y, wB.y);   // kp + 1, col 1
        }
    }

    #pragma unroll
    for (int r = 0; r < 8; r++) {
        const int row = row0 + rbase + r;
        if (row >= NN) continue;
        float2 hv;
        float lo, hi;
        unpack2(acc[r][0], lo, hi); hv.x = lo + hi;
        unpack2(acc[r][1], lo, hi); hv.y = lo + hi;
        *(float2*)(g_h + (size_t)row * F + colbase) = hv;
    }
}

// ============================================================================
// Kernel A2: hc dots — compensated fp32 (Dot2), ZERO fp64 (validated R13).
// block 256 = 8 warps: warps 0-3 -> c1 rows [base..base+32),
//                      warps 4-7 -> c2 same rows. Lane owns cols lane*4..+3.
// ============================================================================
__global__ void __launch_bounds__(256) hc_kernel(
    const float* __restrict__ c1,
    const float* __restrict__ c2)
{
    const unsigned FULL = 0xffffffffu;
    const int warp = threadIdx.x >> 5;
    const int lane = threadIdx.x & 31;
    const bool is2 = warp >= 4;
    const int rowbase = blockIdx.x * 32 + (warp & 3) * 8;
    const int colbase = lane * 4;

    const float* cvec = is2 ? c2 : c1;
    const float4 cc = *(const float4*)(cvec + colbase);

    #pragma unroll
    for (int r = 0; r < 8; r++) {
        const int row = rowbase + r;
        if (row >= NN) break;
        const float4 hv = *(const float4*)(g_h + (size_t)row * F + colbase);

        // local Dot2 over the lane's 4 products
        float s, c, p, e, err;
        twoprod(hv.x, cc.x, s, c);
        twoprod(hv.y, cc.y, p, e);
        twosum(s, p, s, err); c += err + e;
        twoprod(hv.z, cc.z, p, e);
        twosum(s, p, s, err); c += err + e;
        twoprod(hv.w, cc.w, p, e);
        twosum(s, p, s, err); c += err + e;

        // cross-lane df reduction (fp32 shfls)
        #pragma unroll
        for (int off = 16; off > 0; off >>= 1) {
            const float s2 = __shfl_down_sync(FULL, s, off);
            const float c2v = __shfl_down_sync(FULL, c, off);
            twosum(s, s2, s, err);
            c += err + c2v;
        }
        if (lane == 0) {
            const float res = s + c;
            if (is2) g_hc2[row] = res;
            else     g_hc1[row] = res;
        }
    }
}

// ============================================================================
// Kernel B: per-node attention (frozen decision chain since R6).
// R15 change: shifted obtained by shfl_up(csum, 3) — bitwise equal to the
// capture-at-index value (csum of lane-3), ~64 fewer ALU ops per thread.
// ============================================================================
__global__ void __launch_bounds__(256) attn_kernel(
    const int* __restrict__ adj,
    const int* __restrict__ deg,
    float* __restrict__ out)
{
    __shared__ float s_buf[8][KNBR];

    const unsigned FULL = 0xffffffffu;
    const int warp = threadIdx.x >> 5;
    const int lane = threadIdx.x & 31;
    const int m    = blockIdx.x * 8 + warp;   // 6250 * 8 == 50000 exactly

    const int  d     = deg[m];
    const int  a     = adj[(size_t)m * KNBR + lane];
    const bool valid = (lane < d);

    const float NEG_INF = __int_as_float(0xff800000u);

    float e32 = NEG_INF;
    if (valid) {
        const float x = g_hc1[m] + g_hc2[a];   // fp32 add, as reference
        e32 = (x >= 0.f) ? x : 0.2f * x;
    }

    float mx = e32;
    #pragma unroll
    for (int off = 16; off > 0; off >>= 1)
        mx = fmaxf(mx, __shfl_xor_sync(FULL, mx, off));

    const float p = valid ? expf(e32 - mx) : 0.f;

    // ---- pass 1: sequential fp32 sum of p ----
    s_buf[warp][lane] = p;
    __syncwarp();
    float s = 0.f;
    #pragma unroll
    for (int q = 0; q < 8; q++) {
        const float4 v = *(const float4*)&s_buf[warp][q * 4];
        s += v.x; s += v.y; s += v.z; s += v.w;
    }

    const float att = p / s;

    // ---- pass 2: sequential fp32 prefix sum, capture csum at own index ----
    __syncwarp();
    s_buf[warp][lane] = att;
    __syncwarp();
    float run = 0.f, csum = 0.f;
    #pragma unroll
    for (int q = 0; q < 8; q++) {
        const float4 v = *(const float4*)&s_buf[warp][q * 4];
        const int k0 = q * 4;
        run += v.x; if (k0 + 0 == lane) csum = run;
        run += v.y; if (k0 + 1 == lane) csum = run;
        run += v.z; if (k0 + 2 == lane) csum = run;
        run += v.w; if (k0 + 3 == lane) csum = run;
    }

    // shifted = csum of lane-3 (== run after lane-3 adds, bitwise)
    const float shifted = __shfl_up_sync(FULL, csum, WSIZE);

    // win = csum - shifted (fp32, same cancellation as reference);
    // for lane == 2 the reference subtracts its zero padding.
    float win = -1.0f;
    if (lane >= WSIZE - 1 && lane < d)
        win = csum - ((lane >= WSIZE) ? shifted : 0.f);

    // argmax, first occurrence on ties
    float bw = win;
    int   bj = lane;
    #pragma unroll
    for (int off = 16; off > 0; off >>= 1) {
        const float ow = __shfl_down_sync(FULL, bw, off);
        const int   oj = __shfl_down_sync(FULL, bj, off);
        if (ow > bw || (ow == bw && oj < bj)) { bw = ow; bj = oj; }
    }
    const int jstar = __shfl_sync(FULL, bj, 0);

    const float scale = (float)d / 3.0f;
    const float t = (lane >= jstar - (WSIZE - 1) && lane <= jstar) ? att * scale : 0.f;

    const float w0 = __shfl_sync(FULL, t, jstar - 2);
    const float w1 = __shfl_sync(FULL, t, jstar - 1);
    const float w2 = __shfl_sync(FULL, t, jstar);
    const int   a0 = __shfl_sync(FULL, a, jstar - 2);
    const int   a1 = __shfl_sync(FULL, a, jstar - 1);
    const int   a2 = __shfl_sync(FULL, a, jstar);

    const float4 v0 = ((const float4*)(g_h + (size_t)a0 * F))[lane];
    const float4 v1 = ((const float4*)(g_h + (size_t)a1 * F))[lane];
    const float4 v2 = ((const float4*)(g_h + (size_t)a2 * F))[lane];

    float4 o;
    o.x = fmaf(w2, v2.x, fmaf(w1, v1.x, w0 * v0.x));
    o.y = fmaf(w2, v2.y, fmaf(w1, v1.y, w0 * v0.y));
    o.z = fmaf(w2, v2.z, fmaf(w1, v1.z, w0 * v0.z));
    o.w = fmaf(w2, v2.w, fmaf(w1, v1.w, w0 * v0.w));

    o.x = (o.x > 0.f) ? o.x : expm1f(o.x);
    o.y = (o.y > 0.f) ? o.y : expm1f(o.y);
    o.z = (o.z > 0.f) ? o.z : expm1f(o.z);
    o.w = (o.w > 0.f) ? o.w : expm1f(o.w);

    ((float4*)out)[(size_t)m * (F / 4) + lane] = o;
}

extern "C" void kernel_launch(void* const* d_in, const int* in_sizes, int n_in,
                              void* d_out, int out_size) {
    const float* inp = (const float*)d_in[0];
    const float* W   = (const float*)d_in[1];
    const float* c1  = (const float*)d_in[2];
    const float* c2  = (const float*)d_in[3];
    const int*   adj = (const int*)d_in[4];
    const int*   deg = (const int*)d_in[5];
    float*       out = (float*)d_out;

    pack_w_kernel<<<32, 256>>>(W);                          // 8192 threads
    gemm_kernel<<<(NN + RPB - 1) / RPB, 256>>>(inp);        // 1563 blocks
    hc_kernel<<<(NN + 31) / 32, 256>>>(c1, c2);             // 1563 blocks
    attn_kernel<<<NN / 8, 256>>>(adj, deg, out);            // 6250 blocks
}

// round 16
// speedup vs baseline: 2.1687x; 1.0762x over previous
#include <cuda_runtime.h>
#include <math.h>

#define NN 50000          // N_NODES == M_NODES
#define KNBR 32
#define F 128
#define WSIZE 3
#define RPB 32            // rows per block (4 row-groups x 8 rows)

typedef unsigned long long ull;

// Scratch (device globals: allocation-free per harness rules)
__device__ float g_h[(size_t)NN * F];     // h = input @ W  (fp32)
__device__ float g_hc1[NN];               // compensated-fp32 h . c1 (== fl32(exact))
__device__ float g_hc2[NN];               // compensated-fp32 h . c2
__device__ ull   g_Wp[64 * F];            // W pre-packed: (W[2kp][c], W[2kp+1][c])

// ---- packed f32x2 helpers ----
static __device__ __forceinline__ ull pack2(float lo, float hi) {
    ull r;
    asm("mov.b64 %0, {%1, %2};" : "=l"(r) : "f"(lo), "f"(hi));
    return r;
}
static __device__ __forceinline__ void unpack2(ull v, float& lo, float& hi) {
    asm("mov.b64 {%0, %1}, %2;" : "=f"(lo), "=f"(hi) : "l"(v));
}
static __device__ __forceinline__ void ffma2(ull& d, ull a, ull b) {
    asm("fma.rn.f32x2 %0, %1, %2, %0;" : "+l"(d) : "l"(a), "l"(b));
}

// ---- error-free fp32 transforms (Dot2 building blocks) ----
static __device__ __forceinline__ void twoprod(float a, float b, float& p, float& e) {
    p = a * b;
    e = fmaf(a, b, -p);
}
static __device__ __forceinline__ void twosum(float a, float b, float& s, float& err) {
    s = a + b;
    const float z = s - a;
    err = (a - (s - z)) + (b - z);
}

// ============================================================================
// Kernel 0: pre-pack W into even/odd-k f32x2 pairs (64 KB total).
// g_Wp[kp*128 + c] = (W[2kp][c], W[2kp+1][c])
// ============================================================================
__global__ void pack_w_kernel(const float* __restrict__ W)
{
    const int i = blockIdx.x * blockDim.x + threadIdx.x;   // 0..8191
    const int kp  = i >> 7;
    const int col = i & 127;
    g_Wp[i] = pack2(W[(2 * kp) * F + col], W[(2 * kp + 1) * F + col]);
}

// ============================================================================
// Kernel A: h = input @ W  +  fused fp32-Dot2 hc epilogue.
// GEMM ARITHMETIC CONTRACT (bitwise, frozen): for each (row, col),
//   acc.lo = sum over even k ascending of in[k]*W[k][c]
//   acc.hi = sum over odd  k ascending;  h = acc.lo + acc.hi
// hc: Dot2 (compensated fp32) == fl32(exact dot) — identical arithmetic to
// the R13-15 standalone hc kernel, reading h from smem instead of gmem.
// 8 warps/block = 4 row-groups x 2 col-halves; lane owns 2 cols; acc = 32 regs.
// ============================================================================
__global__ void __launch_bounds__(256) gemm_hc_kernel(
    const float* __restrict__ inp,
    const float* __restrict__ c1,
    const float* __restrict__ c2)
{
    __shared__ float s_in[RPB][F];   // 16 KB: input rows, then reused for h

    const int tid  = threadIdx.x;
    const int lane = tid & 31;
    const int warp = tid >> 5;
    const int row0 = blockIdx.x * RPB;

    // stage 32 input rows (1024 float4; 4 per thread)
    #pragma unroll
    for (int i = 0; i < 4; i++) {
        const int idx   = tid + i * 256;
        const int row   = idx >> 5;
        const int chunk = idx & 31;
        int grow = row0 + row;
        if (grow >= NN) grow = NN - 1;         // clamp (tail block)
        ((float4*)&s_in[row][0])[chunk] =
            ((const float4*)(inp + (size_t)grow * F))[chunk];
    }
    __syncthreads();

    ull acc[8][2];
    #pragma unroll
    for (int r = 0; r < 8; r++) { acc[r][0] = 0ULL; acc[r][1] = 0ULL; }

    const int colbase = (warp & 1) * 64 + lane * 2;   // 2 cols per lane
    const int rbase   = (warp >> 1) * 8;              // 8 rows per warp

    #pragma unroll 4
    for (int kp = 0; kp < 64; kp += 2) {       // two kp-pairs per step
        const ulonglong2 wA = *(const ulonglong2*)(g_Wp + kp * F + colbase);
        const ulonglong2 wB = *(const ulonglong2*)(g_Wp + (kp + 1) * F + colbase);
        #pragma unroll
        for (int r = 0; r < 8; r++) {
            // one LDS.128: (s[k],s[k+1]) and (s[k+2],s[k+3])
            const ulonglong2 ipq = *(const ulonglong2*)&s_in[rbase + r][kp * 2];
            ffma2(acc[r][0], ipq.x, wA.x);   // kp    , col 0
            ffma2(acc[r][0], ipq.y, wB.x);   // kp + 1, col 0
            ffma2(acc[r][1], ipq.x, wA.y);   // kp    , col 1
            ffma2(acc[r][1], ipq.y, wB.y);   // kp + 1, col 1
        }
    }

    // finalize h into registers
    float2 hvs[8];
    #pragma unroll
    for (int r = 0; r < 8; r++) {
        float lo, hi;
        unpack2(acc[r][0], lo, hi); hvs[r].x = lo + hi;
        unpack2(acc[r][1], lo, hi); hvs[r].y = lo + hi;
    }

    // all warps done reading staged input before we overwrite s_in with h
    __syncthreads();

    #pragma unroll
    for (int r = 0; r < 8; r++) {
        s_in[rbase + r][colbase]     = hvs[r].x;
        s_in[rbase + r][colbase + 1] = hvs[r].y;
        const int row = row0 + rbase + r;
        if (row < NN)
            *(float2*)(g_h + (size_t)row * F + colbase) = hvs[r];
    }
    __syncthreads();

    // --- fused hc epilogue: Dot2, identical arithmetic to R13's hc kernel ---
    // warps 0-3 -> c1 rows [0..32), warps 4-7 -> c2 same rows;
    // lane owns cols lane*4..+3.
    {
        const unsigned FULL = 0xffffffffu;
        const bool is2 = warp >= 4;
        const int rowb = (warp & 3) * 8;
        const int cb4  = lane * 4;
        const float* cvec = is2 ? c2 : c1;
        const float4 cc = *(const float4*)(cvec + cb4);

        #pragma unroll
        for (int r = 0; r < 8; r++) {
            const int row = row0 + rowb + r;
            const float4 hv = *(const float4*)&s_in[rowb + r][cb4];

            float s, c, p, e, err;
            twoprod(hv.x, cc.x, s, c);
            twoprod(hv.y, cc.y, p, e);
            twosum(s, p, s, err); c += err + e;
            twoprod(hv.z, cc.z, p, e);
            twosum(s, p, s, err); c += err + e;
            twoprod(hv.w, cc.w, p, e);
            twosum(s, p, s, err); c += err + e;

            #pragma unroll
            for (int off = 16; off > 0; off >>= 1) {
                const float s2 = __shfl_down_sync(FULL, s, off);
                const float c2v = __shfl_down_sync(FULL, c, off);
                twosum(s, s2, s, err);
                c += err + c2v;
            }
            if (lane == 0 && row < NN) {
                const float res = s + c;
                if (is2) g_hc2[row] = res;
                else     g_hc1[row] = res;
            }
        }
    }
}

// ============================================================================
// Kernel B: per-node attention (frozen decision chain since R6).
// R16 change: elu via __expf(x)-1 (output-only path, 1e-3 L2 tolerance;
// decisions unaffected). p keeps libdevice expf (decision-critical).
// ============================================================================
__global__ void __launch_bounds__(256) attn_kernel(
    const int* __restrict__ adj,
    const int* __restrict__ deg,
    float* __restrict__ out)
{
    __shared__ float s_buf[8][KNBR];

    const unsigned FULL = 0xffffffffu;
    const int warp = threadIdx.x >> 5;
    const int lane = threadIdx.x & 31;
    const int m    = blockIdx.x * 8 + warp;   // 6250 * 8 == 50000 exactly

    const int  d     = deg[m];
    const int  a     = adj[(size_t)m * KNBR + lane];
    const bool valid = (lane < d);

    const float NEG_INF = __int_as_float(0xff800000u);

    float e32 = NEG_INF;
    if (valid) {
        const float x = g_hc1[m] + g_hc2[a];   // fp32 add, as reference
        e32 = (x >= 0.f) ? x : 0.2f * x;
    }

    float mx = e32;
    #pragma unroll
    for (int off = 16; off > 0; off >>= 1)
        mx = fmaxf(mx, __shfl_xor_sync(FULL, mx, off));

    const float p = valid ? expf(e32 - mx) : 0.f;

    // ---- pass 1: sequential fp32 sum of p ----
    s_buf[warp][lane] = p;
    __syncwarp();
    float s = 0.f;
    #pragma unroll
    for (int q = 0; q < 8; q++) {
        const float4 v = *(const float4*)&s_buf[warp][q * 4];
        s += v.x; s += v.y; s += v.z; s += v.w;
    }

    const float att = p / s;

    // ---- pass 2: sequential fp32 prefix sum, capture csum at own index ----
    __syncwarp();
    s_buf[warp][lane] = att;
    __syncwarp();
    float run = 0.f, csum = 0.f;
    #pragma unroll
    for (int q = 0; q < 8; q++) {
        const float4 v = *(const float4*)&s_buf[warp][q * 4];
        const int k0 = q * 4;
        run += v.x; if (k0 + 0 == lane) csum = run;
        run += v.y; if (k0 + 1 == lane) csum = run;
        run += v.z; if (k0 + 2 == lane) csum = run;
        run += v.w; if (k0 + 3 == lane) csum = run;
    }

    // shifted = csum of lane-3 (bitwise)
    const float shifted = __shfl_up_sync(FULL, csum, WSIZE);

    float win = -1.0f;
    if (lane >= WSIZE - 1 && lane < d)
        win = csum - ((lane >= WSIZE) ? shifted : 0.f);

    // argmax, first occurrence on ties
    float bw = win;
    int   bj = lane;
    #pragma unroll
    for (int off = 16; off > 0; off >>= 1) {
        const float ow = __shfl_down_sync(FULL, bw, off);
        const int   oj = __shfl_down_sync(FULL, bj, off);
        if (ow > bw || (ow == bw && oj < bj)) { bw = ow; bj = oj; }
    }
    const int jstar = __shfl_sync(FULL, bj, 0);

    const float scale = (float)d / 3.0f;
    const float t = (lane >= jstar - (WSIZE - 1) && lane <= jstar) ? att * scale : 0.f;

    const float w0 = __shfl_sync(FULL, t, jstar - 2);
    const float w1 = __shfl_sync(FULL, t, jstar - 1);
    const float w2 = __shfl_sync(FULL, t, jstar);
    const int   a0 = __shfl_sync(FULL, a, jstar - 2);
    const int   a1 = __shfl_sync(FULL, a, jstar - 1);
    const int   a2 = __shfl_sync(FULL, a, jstar);

    const float4 v0 = ((const float4*)(g_h + (size_t)a0 * F))[lane];
    const float4 v1 = ((const float4*)(g_h + (size_t)a1 * F))[lane];
    const float4 v2 = ((const float4*)(g_h + (size_t)a2 * F))[lane];

    float4 o;
    o.x = fmaf(w2, v2.x, fmaf(w1, v1.x, w0 * v0.x));
    o.y = fmaf(w2, v2.y, fmaf(w1, v1.y, w0 * v0.y));
    o.z = fmaf(w2, v2.z, fmaf(w1, v1.z, w0 * v0.z));
    o.w = fmaf(w2, v2.w, fmaf(w1, v1.w, w0 * v0.w));

    // elu: output-only path — fast exp is fine under the 1e-3 L2 threshold
    o.x = (o.x > 0.f) ? o.x : (__expf(o.x) - 1.0f);
    o.y = (o.y > 0.f) ? o.y : (__expf(o.y) - 1.0f);
    o.z = (o.z > 0.f) ? o.z : (__expf(o.z) - 1.0f);
    o.w = (o.w > 0.f) ? o.w : (__expf(o.w) - 1.0f);

    ((float4*)out)[(size_t)m * (F / 4) + lane] = o;
}

extern "C" void kernel_launch(void* const* d_in, const int* in_sizes, int n_in,
                              void* d_out, int out_size) {
    const float* inp = (const float*)d_in[0];
    const float* W   = (const float*)d_in[1];
    const float* c1  = (const float*)d_in[2];
    const float* c2  = (const float*)d_in[3];
    const int*   adj = (const int*)d_in[4];
    const int*   deg = (const int*)d_in[5];
    float*       out = (float*)d_out;

    pack_w_kernel<<<32, 256>>>(W);                             // 8192 threads
    gemm_hc_kernel<<<(NN + RPB - 1) / RPB, 256>>>(inp, c1, c2); // 1563 blocks
    attn_kernel<<<NN / 8, 256>>>(adj, deg, out);               // 6250 blocks
}

// round 17
// speedup vs baseline: 2.2925x; 1.0571x over previous
#include <cuda_runtime.h>
#include <math.h>

#define NN 50000          // N_NODES == M_NODES
#define KNBR 32
#define F 128
#define WSIZE 3
#define RPB 32            // rows per block (4 row-groups x 2 col-halves)

typedef unsigned long long ull;

// Scratch (device globals: allocation-free per harness rules)
__device__ float g_h[(size_t)NN * F];     // h = input @ W  (fp32)
__device__ float g_hc1[NN];               // compensated-fp32 h . c1 (== fl32(exact))
__device__ float g_hc2[NN];               // compensated-fp32 h . c2
__device__ ull   g_Wp[64 * F];            // W pre-packed: (W[2kp][c], W[2kp+1][c])

// ---- packed f32x2 helpers ----
static __device__ __forceinline__ ull pack2(float lo, float hi) {
    ull r;
    asm("mov.b64 %0, {%1, %2};" : "=l"(r) : "f"(lo), "f"(hi));
    return r;
}
static __device__ __forceinline__ void unpack2(ull v, float& lo, float& hi) {
    asm("mov.b64 {%0, %1}, %2;" : "=f"(lo), "=f"(hi) : "l"(v));
}
static __device__ __forceinline__ void ffma2(ull& d, ull a, ull b) {
    asm("fma.rn.f32x2 %0, %1, %2, %0;" : "+l"(d) : "l"(a), "l"(b));
}

// ---- error-free fp32 transforms (Dot2 building blocks) ----
static __device__ __forceinline__ void twoprod(float a, float b, float& p, float& e) {
    p = a * b;
    e = fmaf(a, b, -p);
}
static __device__ __forceinline__ void twosum(float a, float b, float& s, float& err) {
    s = a + b;
    const float z = s - a;
    err = (a - (s - z)) + (b - z);
}

// ============================================================================
// Kernel 0: pre-pack W into even/odd-k f32x2 pairs (64 KB total).
// g_Wp[kp*128 + c] = (W[2kp][c], W[2kp+1][c])
// ============================================================================
__global__ void pack_w_kernel(const float* __restrict__ W)
{
    const int i = blockIdx.x * blockDim.x + threadIdx.x;   // 0..8191
    const int kp  = i >> 7;
    const int col = i & 127;
    g_Wp[i] = pack2(W[(2 * kp) * F + col], W[(2 * kp + 1) * F + col]);
}

// ============================================================================
// Kernel A: h = input @ W  +  fused fp32-Dot2 hc epilogue (R16-validated).
// GEMM ARITHMETIC CONTRACT (bitwise, frozen): for each (row, col),
//   acc.lo = sum over even k ascending of in[k]*W[k][c]
//   acc.hi = sum over odd  k ascending;  h = acc.lo + acc.hi
// R17 change: unroll 8 (deeper LDG MLP); arithmetic untouched.
// ============================================================================
__global__ void __launch_bounds__(256) gemm_hc_kernel(
    const float* __restrict__ inp,
    const float* __restrict__ c1,
    const float* __restrict__ c2)
{
    __shared__ float s_in[RPB][F];   // 16 KB: input rows, then reused for h

    const int tid  = threadIdx.x;
    const int lane = tid & 31;
    const int warp = tid >> 5;
    const int row0 = blockIdx.x * RPB;

    // stage 32 input rows (1024 float4; 4 per thread)
    #pragma unroll
    for (int i = 0; i < 4; i++) {
        const int idx   = tid + i * 256;
        const int row   = idx >> 5;
        const int chunk = idx & 31;
        int grow = row0 + row;
        if (grow >= NN) grow = NN - 1;         // clamp (tail block)
        ((float4*)&s_in[row][0])[chunk] =
            ((const float4*)(inp + (size_t)grow * F))[chunk];
    }
    __syncthreads();

    ull acc[8][2];
    #pragma unroll
    for (int r = 0; r < 8; r++) { acc[r][0] = 0ULL; acc[r][1] = 0ULL; }

    const int colbase = (warp & 1) * 64 + lane * 2;   // 2 cols per lane
    const int rbase   = (warp >> 1) * 8;              // 8 rows per warp

    #pragma unroll 8
    for (int kp = 0; kp < 64; kp += 2) {       // two kp-pairs per step
        const ulonglong2 wA = *(const ulonglong2*)(g_Wp + kp * F + colbase);
        const ulonglong2 wB = *(const ulonglong2*)(g_Wp + (kp + 1) * F + colbase);
        #pragma unroll
        for (int r = 0; r < 8; r++) {
            // one LDS.128: (s[k],s[k+1]) and (s[k+2],s[k+3])
            const ulonglong2 ipq = *(const ulonglong2*)&s_in[rbase + r][kp * 2];
            ffma2(acc[r][0], ipq.x, wA.x);   // kp    , col 0
            ffma2(acc[r][0], ipq.y, wB.x);   // kp + 1, col 0
            ffma2(acc[r][1], ipq.x, wA.y);   // kp    , col 1
            ffma2(acc[r][1], ipq.y, wB.y);   // kp + 1, col 1
        }
    }

    // finalize h into registers
    float2 hvs[8];
    #pragma unroll
    for (int r = 0; r < 8; r++) {
        float lo, hi;
        unpack2(acc[r][0], lo, hi); hvs[r].x = lo + hi;
        unpack2(acc[r][1], lo, hi); hvs[r].y = lo + hi;
    }

    // all warps done reading staged input before we overwrite s_in with h
    __syncthreads();

    #pragma unroll
    for (int r = 0; r < 8; r++) {
        s_in[rbase + r][colbase]     = hvs[r].x;
        s_in[rbase + r][colbase + 1] = hvs[r].y;
        const int row = row0 + rbase + r;
        if (row < NN)
            *(float2*)(g_h + (size_t)row * F + colbase) = hvs[r];
    }
    __syncthreads();

    // --- fused hc epilogue: Dot2, identical arithmetic to R13's hc kernel ---
    {
        const unsigned FULL = 0xffffffffu;
        const bool is2 = warp >= 4;
        const int rowb = (warp & 3) * 8;
        const int cb4  = lane * 4;
        const float* cvec = is2 ? c2 : c1;
        const float4 cc = *(const float4*)(cvec + cb4);

        #pragma unroll
        for (int r = 0; r < 8; r++) {
            const int row = row0 + rowb + r;
            const float4 hv = *(const float4*)&s_in[rowb + r][cb4];

            float s, c, p, e, err;
            twoprod(hv.x, cc.x, s, c);
            twoprod(hv.y, cc.y, p, e);
            twosum(s, p, s, err); c += err + e;
            twoprod(hv.z, cc.z, p, e);
            twosum(s, p, s, err); c += err + e;
            twoprod(hv.w, cc.w, p, e);
            twosum(s, p, s, err); c += err + e;

            #pragma unroll
            for (int off = 16; off > 0; off >>= 1) {
                const float s2 = __shfl_down_sync(FULL, s, off);
                const float c2v = __shfl_down_sync(FULL, c, off);
                twosum(s, s2, s, err);
                c += err + c2v;
            }
            if (lane == 0 && row < NN) {
                const float res = s + c;
                if (is2) g_hc2[row] = res;
                else     g_hc1[row] = res;
            }
        }
    }
}

// ============================================================================
// Kernel B: per-node attention (frozen decision chain since R6).
// R17 change: pass-2 prefix computed once by lane 0 in-place in smem (same
// fp32 add sequence, bit-identical csum) instead of per-lane capture-at-index
// — removes ~64 ISETP/SEL warp-instructions.
// ============================================================================
__global__ void __launch_bounds__(256) attn_kernel(
    const int* __restrict__ adj,
    const int* __restrict__ deg,
    float* __restrict__ out)
{
    __shared__ float s_buf[8][KNBR];

    const unsigned FULL = 0xffffffffu;
    const int warp = threadIdx.x >> 5;
    const int lane = threadIdx.x & 31;
    const int m    = blockIdx.x * 8 + warp;   // 6250 * 8 == 50000 exactly

    const int  d     = deg[m];
    const int  a     = adj[(size_t)m * KNBR + lane];
    const bool valid = (lane < d);

    const float NEG_INF = __int_as_float(0xff800000u);

    float e32 = NEG_INF;
    if (valid) {
        const float x = g_hc1[m] + g_hc2[a];   // fp32 add, as reference
        e32 = (x >= 0.f) ? x : 0.2f * x;
    }

    float mx = e32;
    #pragma unroll
    for (int off = 16; off > 0; off >>= 1)
        mx = fmaxf(mx, __shfl_xor_sync(FULL, mx, off));

    const float p = valid ? expf(e32 - mx) : 0.f;

    // ---- pass 1: sequential fp32 sum of p ----
    s_buf[warp][lane] = p;
    __syncwarp();
    float s = 0.f;
    #pragma unroll
    for (int q = 0; q < 8; q++) {
        const float4 v = *(const float4*)&s_buf[warp][q * 4];
        s += v.x; s += v.y; s += v.z; s += v.w;
    }

    const float att = p / s;

    // ---- pass 2: sequential fp32 prefix, computed once by lane 0 ----
    // In-place: each float4 is read before its slot is overwritten with the
    // running prefixes. Add order identical to the reference cumsum.
    __syncwarp();
    s_buf[warp][lane] = att;
    __syncwarp();
    if (lane == 0) {
        float run = 0.f;
        #pragma unroll
        for (int q = 0; q < 8; q++) {
            const float4 v = *(const float4*)&s_buf[warp][q * 4];
            float4 o;
            run += v.x; o.x = run;
            run += v.y; o.y = run;
            run += v.z; o.z = run;
            run += v.w; o.w = run;
            *(float4*)&s_buf[warp][q * 4] = o;
        }
    }
    __syncwarp();
    const float csum = s_buf[warp][lane];

    // shifted = csum of lane-3 (bitwise)
    const float shifted = __shfl_up_sync(FULL, csum, WSIZE);

    float win = -1.0f;
    if (lane >= WSIZE - 1 && lane < d)
        win = csum - ((lane >= WSIZE) ? shifted : 0.f);

    // argmax, first occurrence on ties
    float bw = win;
    int   bj = lane;
    #pragma unroll
    for (int off = 16; off > 0; off >>= 1) {
        const float ow = __shfl_down_sync(FULL, bw, off);
        const int   oj = __shfl_down_sync(FULL, bj, off);
        if (ow > bw || (ow == bw && oj < bj)) { bw = ow; bj = oj; }
    }
    const int jstar = __shfl_sync(FULL, bj, 0);

    const float scale = (float)d / 3.0f;
    const float t = (lane >= jstar - (WSIZE - 1) && lane <= jstar) ? att * scale : 0.f;

    const float w0 = __shfl_sync(FULL, t, jstar - 2);
    const float w1 = __shfl_sync(FULL, t, jstar - 1);
    const float w2 = __shfl_sync(FULL, t, jstar);
    const int   a0 = __shfl_sync(FULL, a, jstar - 2);
    const int   a1 = __shfl_sync(FULL, a, jstar - 1);
    const int   a2 = __shfl_sync(FULL, a, jstar);

    const float4 v0 = ((const float4*)(g_h + (size_t)a0 * F))[lane];
    const float4 v1 = ((const float4*)(g_h + (size_t)a1 * F))[lane];
    const float4 v2 = ((const float4*)(g_h + (size_t)a2 * F))[lane];

    float4 o;
    o.x = fmaf(w2, v2.x, fmaf(w1, v1.x, w0 * v0.x));
    o.y = fmaf(w2, v2.y, fmaf(w1, v1.y, w0 * v0.y));
    o.z = fmaf(w2, v2.z, fmaf(w1, v1.z, w0 * v0.z));
    o.w = fmaf(w2, v2.w, fmaf(w1, v1.w, w0 * v0.w));

    // elu: output-only path — fast exp under the 1e-3 L2 threshold
    o.x = (o.x > 0.f) ? o.x : (__expf(o.x) - 1.0f);
    o.y = (o.y > 0.f) ? o.y : (__expf(o.y) - 1.0f);
    o.z = (o.z > 0.f) ? o.z : (__expf(o.z) - 1.0f);
    o.w = (o.w > 0.f) ? o.w : (__expf(o.w) - 1.0f);

    ((float4*)out)[(size_t)m * (F / 4) + lane] = o;
}

extern "C" void kernel_launch(void* const* d_in, const int* in_sizes, int n_in,
                              void* d_out, int out_size) {
    const float* inp = (const float*)d_in[0];
    const float* W   = (const float*)d_in[1];
    const float* c1  = (const float*)d_in[2];
    const float* c2  = (const float*)d_in[3];
    const int*   adj = (const int*)d_in[4];
    const int*   deg = (const int*)d_in[5];
    float*       out = (float*)d_out;

    pack_w_kernel<<<32, 256>>>(W);                              // 8192 threads
    gemm_hc_kernel<<<(NN + RPB - 1) / RPB, 256>>>(inp, c1, c2); // 1563 blocks
    attn_kernel<<<NN / 8, 256>>>(adj, deg, out);                // 6250 blocks
}